// round 11
// baseline (speedup 1.0000x reference)
#include <cuda_runtime.h>

// reblurWithKernel: spatially-varying 33x33 blur, per-4x4-block kernels.
// out[c,h,w] = sum_{u,v} in[clamp(h+u-16),clamp(w+v-16)] * K[u*33+v, h/4, w/4]
//
// R10: scalar-FFMA inner loop (R9 FFMA2 regressed) + fine-grained persistent
// scheduling to fix the 86.5% wave fill (512 tiles vs 296 CTA slots; 148=4*37
// never divides 2^k). 2048 tiles of 8 wb-blocks x 1 hb, pulled via an atomic
// ticket by 444 persistent CTAs (2 resident/SM) -> ~6.9 items/worker, ~99% fill.
// CTA = 384 thr = 12 warps = (u mod 4) x (tap-third p: 11 taps), channels
// merged inside each warp (kernel rows loaded once per (q,p), not per channel).
// Lane = (wb-block b, output-row oi). Combine 12 warp-partials via smem.

#define KW    33
#define BLK   4
#define PAD   16
#define HH    512
#define WW    512
#define HB    128
#define WBN   128
#define KSTR  (HB*WBN)          // 16384 elements between taps
#define TWB   8                 // wb blocks per tile
#define NTILES (HB * (WBN/TWB)) // 2048
#define PROWS 36
#define PCOLS 64
#define PSTR  68                // padded row stride (floats)
#define ROWSZ (PROWS*PSTR)      // 2448 floats per channel
#define NTH   384
#define NCTAS 444

__device__ unsigned int g_ticket;

__global__ void reset_ticket_kernel() {
    if (threadIdx.x == 0) g_ticket = 0u;
}

// Compute all u-rows (u = q mod 4) for tap-range [11P, 11P+10], 3 channels.
// ROFF/NLD compile-time so the register window rb[] stays in registers.
template<int P>
__device__ __forceinline__ void compute_u(const float* __restrict__ sp,
                                          const float* __restrict__ kb,
                                          int q, int oi, int colstart,
                                          float acc[3][4])
{
    constexpr int VOFF = 11 * P;
    constexpr int ROFF = (P == 0) ? 0 : (P == 1 ? 3 : 2);
    constexpr int NLD  = (P == 1) ? 5 : 4;

#pragma unroll 1
    for (int u = q; u < KW; u += 4) {
        float kr[11];
        const float* kp = kb + (u * KW + VOFF) * KSTR;
#pragma unroll
        for (int v = 0; v < 11; v++)
            kr[v] = __ldg(kp + v * KSTR);

#pragma unroll
        for (int c = 0; c < 3; c++) {
            float rb[4 * NLD];
            const float4* rp = reinterpret_cast<const float4*>(
                sp + c * ROWSZ + (u + oi) * PSTR + colstart);
#pragma unroll
            for (int i = 0; i < NLD; i++) {
                float4 x = rp[i];
                rb[4*i+0] = x.x; rb[4*i+1] = x.y;
                rb[4*i+2] = x.z; rb[4*i+3] = x.w;
            }
#pragma unroll
            for (int v = 0; v < 11; v++) {
                const float k = kr[v];
                acc[c][0] += k * rb[ROFF + v + 0];
                acc[c][1] += k * rb[ROFF + v + 1];
                acc[c][2] += k * rb[ROFF + v + 2];
                acc[c][3] += k * rb[ROFF + v + 3];
            }
        }
    }
}

__global__ __launch_bounds__(NTH, 2)
void reblur_kernel(const float* __restrict__ img,
                   const float* __restrict__ ker,
                   float* __restrict__ out)
{
    __shared__ __align__(16) float sp[3 * ROWSZ];   // 7344 floats = 29.4 KB
    __shared__ int s_tile;

    const int tid  = threadIdx.x;
    const int w    = tid >> 5;
    const int lane = tid & 31;
    const int q    = w & 3;        // u mod 4
    const int p    = w >> 2;       // tap-third 0..2
    const int b    = lane & 7;     // wb block within tile
    const int oi   = lane >> 3;    // output row within block

    // window start column per p (16B aligned: 16b, 16b+32, 16b+80 bytes)
    const int colstart = (p == 0) ? 4*b : (p == 1 ? 4*b + 8 : 4*b + 20);

    for (;;) {
        if (tid == 0) s_tile = (int)atomicAdd(&g_ticket, 1u);
        __syncthreads();
        const int t = s_tile;
        if (t >= NTILES) break;                // uniform exit

        const int hb  = t >> 4;
        const int wb0 = (t & 15) * TWB;

        // ---- cooperative patch load (edge-clamped), 3 channels ----
        const int row0 = hb  * BLK - PAD;
        const int col0 = wb0 * BLK - PAD;
        for (int idx = tid; idx < 3 * PROWS * PCOLS; idx += NTH) {
            int c   = idx / (PROWS * PCOLS);
            int rem = idx - c * (PROWS * PCOLS);
            int r   = rem / PCOLS;
            int cc  = rem - r * PCOLS;
            int ir  = min(max(row0 + r, 0), HH - 1);
            int ic  = min(max(col0 + cc, 0), WW - 1);
            sp[c * ROWSZ + r * PSTR + cc] = img[c * (HH * WW) + ir * WW + ic];
        }
        __syncthreads();

        float acc[3][4];
#pragma unroll
        for (int c = 0; c < 3; c++)
#pragma unroll
            for (int j = 0; j < 4; j++)
                acc[c][j] = 0.0f;

        const float* kb = ker + hb * WBN + (wb0 + b);
        if      (p == 0) compute_u<0>(sp, kb, q, oi, colstart, acc);
        else if (p == 1) compute_u<1>(sp, kb, q, oi, colstart, acc);
        else             compute_u<2>(sp, kb, q, oi, colstart, acc);

        // ---- combine 12 warp-partials via smem (overlay patch region) ----
        __syncthreads();                        // all done reading patch
        // red[(w*32+lane)*12 + (c*4+oj)], 4608 floats
#pragma unroll
        for (int c = 0; c < 3; c++)
#pragma unroll
            for (int j = 0; j < 4; j++)
                sp[(w * 32 + lane) * 12 + c * 4 + j] = acc[c][j];
        __syncthreads();

        // 384 threads: thread = (lane2, k); sum over 12 warps; stage result
        {
            const int lane2 = tid / 12;         // 0..31 -> (b2, oi2)
            const int k     = tid - lane2 * 12; // 0..11 -> (c2, oj2)
            float s = 0.0f;
#pragma unroll
            for (int ww2 = 0; ww2 < 12; ww2++)
                s += sp[(ww2 * 32 + lane2) * 12 + k];
            const int b2  = lane2 & 7;
            const int oi2 = lane2 >> 3;
            const int c2  = k >> 2;
            const int oj2 = k & 3;
            // stage at sp + 4608: [(c*4+oi)*8 + b]*4 + oj  (384 floats)
            sp[4608 + (((c2 * 4 + oi2) * 8 + b2) * 4 + oj2)] = s;
        }
        __syncthreads();

        // ---- 96 threads store float4 rows (8 lanes x 16B = 128B contig) ----
        if (tid < 96) {
            const int c3  = tid >> 5;           // 0..2
            const int rem = tid & 31;
            const int oi3 = rem >> 3;           // 0..3
            const int b3  = rem & 7;            // 0..7
            const float4 val = *reinterpret_cast<const float4*>(
                sp + 4608 + ((c3 * 4 + oi3) * 8 + b3) * 4);
            float* ob = out + c3 * (HH * WW)
                      + (hb * BLK + oi3) * WW + (wb0 + b3) * BLK;
            *reinterpret_cast<float4*>(ob) = val;
        }
        __syncthreads();                        // protect stage before reuse
    }
}

extern "C" void kernel_launch(void* const* d_in, const int* in_sizes, int n_in,
                              void* d_out, int out_size)
{
    const float* img = (const float*)d_in[0];  // (1,3,512,512) fp32
    const float* ker = (const float*)d_in[1];  // (1,1089,128,128) fp32
    float* out = (float*)d_out;                // (1,3,512,512) fp32
    (void)in_sizes; (void)n_in; (void)out_size;

    reset_ticket_kernel<<<1, 32>>>();
    reblur_kernel<<<NCTAS, NTH>>>(img, ker, out);
}

// round 13
// speedup vs baseline: 1.3507x; 1.3507x over previous
#include <cuda_runtime.h>

// reblurWithKernel: spatially-varying 33x33 blur, per-4x4-block kernels.
// out[c,h,w] = sum_{u,v} in[clamp(h+u-16),clamp(w+v-16)] * K[u*33+v, h/4, w/4]
//
// R11 = R7 (best: 32-wb x 1-hb tile, lane = wb so kernel LDGs are one 128B
// wavefront, 12 warps = 3 channels x 4 u-quarters) plus:
//  (1) software-pipelined kernel-row loads in two halves (krA: taps 0..16,
//      krB: taps 17..32): load krB(u) -> compute halfA -> prefetch krA(u+4)
//      -> compute halfB. Kills the long_scoreboard stall on kr at each u head
//      (issue was 58%). LDS cost/u: 40 vs 36 LDS.128 (+11%).
//  (2) row u=32 balanced across the 4 q-warps (8 taps each, q=3 adds tap 32):
//      every warp does 8 u-rows + 1/4 row instead of 9-vs-8 imbalance (-8%
//      CTA makespan).

#define KW     33
#define BLK    4
#define PAD    16
#define HH     512
#define WW     512
#define HB     128
#define WBNUM  128
#define KSTR   (HB*WBNUM)         // 16384 elements between taps
#define TWB    32                 // wb blocks per CTA
#define PROWS  36                 // 4 + 2*16
#define PCOLS  160                // 32*4 + 2*16
#define PSTR   164                // row stride (floats), 16B-aligned
#define NTHREADS 384
#define SMEM_FLOATS (3 * PROWS * PSTR)
#define SMEM_BYTES  (SMEM_FLOATS * 4)

__global__ __launch_bounds__(NTHREADS, 2)
void reblur_kernel(const float* __restrict__ img,
                   const float* __restrict__ ker,
                   float* __restrict__ out)
{
    extern __shared__ __align__(16) float sm[];

    const int tid = threadIdx.x;
    const int WB0 = blockIdx.x * TWB;
    const int HB0 = blockIdx.y;

    // ---- work mapping: 12 warps = 3 channels x 4 u-quarters ----
    const int w    = tid >> 5;
    const int lane = tid & 31;    // wb block within tile
    const int c    = w >> 2;      // 0..2 channel
    const int q    = w & 3;       // 0..3 u-quarter (u = q mod 4, u < 32)
    const int wb4  = lane * BLK;

    // Kernels element offset for tap t: t*KSTR + hb*WBNUM + wb
    // 32 lanes -> 32 consecutive wb -> one contiguous 128B wavefront per LDG.
    const float* kbase = ker + HB0 * WBNUM + (WB0 + lane);

    // ---- preload krA for first u (= q) before the smem barrier ----
    float krA[17], krB[16];
    {
        const float* kp = kbase + (q * KW) * KSTR;
#pragma unroll
        for (int v = 0; v < 17; v++)
            krA[v] = __ldg(kp + v * KSTR);
    }

    // ---- cooperative patch load (edge-clamped), 3 channels ----
    const int row0 = HB0 * BLK - PAD;
    const int col0 = WB0 * BLK - PAD;
    for (int idx = tid; idx < 3 * PROWS * PCOLS; idx += NTHREADS) {
        int cc0 = idx / (PROWS * PCOLS);
        int rem = idx - cc0 * (PROWS * PCOLS);
        int r   = rem / PCOLS;
        int cc  = rem - r * PCOLS;
        int ir  = min(max(row0 + r, 0), HH - 1);
        int ic  = min(max(col0 + cc, 0), WW - 1);
        sm[cc0 * (PROWS * PSTR) + r * PSTR + cc] = img[cc0 * (HH * WW) + ir * WW + ic];
    }
    __syncthreads();

    const float* spc = sm + c * (PROWS * PSTR);

    float acc[4][4];
#pragma unroll
    for (int i = 0; i < 4; i++)
#pragma unroll
        for (int j = 0; j < 4; j++)
            acc[i][j] = 0.0f;

    // ---- main loop: u = q, q+4, ..., 28/29/30/31 (8 iterations each) ----
#pragma unroll 1
    for (int u = q; u < 32; u += 4) {
        const float* kpu = kbase + (u * KW) * KSTR;
        // load krB (taps 17..32) — consumed only after halfA compute
#pragma unroll
        for (int v = 0; v < 16; v++)
            krB[v] = __ldg(kpu + (17 + v) * KSTR);

        // compute halfA: taps 0..16, window cols 0..19
#pragma unroll
        for (int oi = 0; oi < 4; oi++) {
            float rb[20];
            const float4* rp =
                reinterpret_cast<const float4*>(spc + (u + oi) * PSTR + wb4);
#pragma unroll
            for (int i = 0; i < 5; i++) {
                float4 t = rp[i];
                rb[4*i+0] = t.x; rb[4*i+1] = t.y;
                rb[4*i+2] = t.z; rb[4*i+3] = t.w;
            }
#pragma unroll
            for (int v = 0; v < 17; v++) {
                const float k = krA[v];
                acc[oi][0] += k * rb[v + 0];
                acc[oi][1] += k * rb[v + 1];
                acc[oi][2] += k * rb[v + 2];
                acc[oi][3] += k * rb[v + 3];
            }
        }

        // prefetch krA for u+4 (hidden under halfB compute)
        if (u + 4 < 32) {
            const float* kp2 = kbase + ((u + 4) * KW) * KSTR;
#pragma unroll
            for (int v = 0; v < 17; v++)
                krA[v] = __ldg(kp2 + v * KSTR);
        }

        // compute halfB: taps 17..32, window cols 16..35 (rb2[k] = col 16+k)
#pragma unroll
        for (int oi = 0; oi < 4; oi++) {
            float rb2[20];
            const float4* rp =
                reinterpret_cast<const float4*>(spc + (u + oi) * PSTR + wb4 + 16);
#pragma unroll
            for (int i = 0; i < 5; i++) {
                float4 t = rp[i];
                rb2[4*i+0] = t.x; rb2[4*i+1] = t.y;
                rb2[4*i+2] = t.z; rb2[4*i+3] = t.w;
            }
#pragma unroll
            for (int v = 0; v < 16; v++) {
                const float k = krB[v];
                acc[oi][0] += k * rb2[v + 1];
                acc[oi][1] += k * rb2[v + 2];
                acc[oi][2] += k * rb2[v + 3];
                acc[oi][3] += k * rb2[v + 4];
            }
        }
    }

    // ---- row u=32, split across q-warps: taps 8q..8q+7 (+ tap 32 for q=3) ----
    {
        float krS[9];
        const float* kp = kbase + (32 * KW + 8 * q) * KSTR;
#pragma unroll
        for (int i = 0; i < 8; i++)
            krS[i] = __ldg(kp + i * KSTR);
        krS[8] = (q == 3) ? __ldg(kbase + (32 * KW + 32) * KSTR) : 0.0f;

#pragma unroll
        for (int oi = 0; oi < 4; oi++) {
            float rbS[12];   // cols (rel wb4) 8q .. 8q+11
            const float4* rp =
                reinterpret_cast<const float4*>(spc + (32 + oi) * PSTR + wb4 + 8 * q);
#pragma unroll
            for (int i = 0; i < 3; i++) {
                float4 t = rp[i];
                rbS[4*i+0] = t.x; rbS[4*i+1] = t.y;
                rbS[4*i+2] = t.z; rbS[4*i+3] = t.w;
            }
#pragma unroll
            for (int i = 0; i < 8; i++) {
                const float k = krS[i];
                acc[oi][0] += k * rbS[i + 0];
                acc[oi][1] += k * rbS[i + 1];
                acc[oi][2] += k * rbS[i + 2];
                acc[oi][3] += k * rbS[i + 3];
            }
            // tap v=32 (krS[8]==0 for q<3): cols 32..35 -> rbS[8..11]
            acc[oi][0] += krS[8] * rbS[8];
            acc[oi][1] += krS[8] * rbS[9];
            acc[oi][2] += krS[8] * rbS[10];
            acc[oi][3] += krS[8] * rbS[11];
        }
    }

    // ---- combine the 4 u-quarters via smem (reuse patch buffer) ----
    __syncthreads();               // everyone done reading the patch
    const int unit = c * 32 + lane;        // 0..95
    if (q != 0) {
        float* dst = sm + ((q - 1) * 96 + unit) * 16;
#pragma unroll
        for (int oi = 0; oi < 4; oi++) {
            float4 v = make_float4(acc[oi][0], acc[oi][1], acc[oi][2], acc[oi][3]);
            *reinterpret_cast<float4*>(dst + oi * 4) = v;
        }
    }
    __syncthreads();
    if (q == 0) {
#pragma unroll
        for (int p = 0; p < 3; p++) {
            const float* src = sm + (p * 96 + unit) * 16;
#pragma unroll
            for (int oi = 0; oi < 4; oi++) {
                float4 o = *reinterpret_cast<const float4*>(src + oi * 4);
                acc[oi][0] += o.x; acc[oi][1] += o.y;
                acc[oi][2] += o.z; acc[oi][3] += o.w;
            }
        }
        // coalesced store: 32 lanes x 16B = 512B contiguous per row
        float* ob = out + c * (HH * WW) + (HB0 * BLK) * WW + (WB0 + lane) * BLK;
#pragma unroll
        for (int oi = 0; oi < 4; oi++) {
            float4 val = make_float4(acc[oi][0], acc[oi][1], acc[oi][2], acc[oi][3]);
            *reinterpret_cast<float4*>(ob + oi * WW) = val;
        }
    }
}

extern "C" void kernel_launch(void* const* d_in, const int* in_sizes, int n_in,
                              void* d_out, int out_size)
{
    const float* img = (const float*)d_in[0];  // (1,3,512,512) fp32
    const float* ker = (const float*)d_in[1];  // (1,1089,128,128) fp32
    float* out = (float*)d_out;                // (1,3,512,512) fp32
    (void)in_sizes; (void)n_in; (void)out_size;

    cudaFuncSetAttribute(reblur_kernel,
                         cudaFuncAttributeMaxDynamicSharedMemorySize, SMEM_BYTES);

    dim3 grid(WBNUM / TWB, HB);  // (4, 128) = 512 CTAs
    reblur_kernel<<<grid, NTHREADS, SMEM_BYTES>>>(img, ker, out);
}

// round 14
// speedup vs baseline: 1.5529x; 1.1497x over previous
#include <cuda_runtime.h>

// reblurWithKernel: spatially-varying 33x33 blur, per-4x4-block kernels.
// out[c,h,w] = sum_{u,v} in[clamp(h+u-16),clamp(w+v-16)] * K[u*33+v, h/4, w/4]
//
// R12 = R11 (32-wb x 1-hb tile, lane = wb -> 128B kernel LDG wavefronts;
// 12 warps = 3 channels x 4 u-quarters; software-pipelined kr halves;
// u=32 row balanced across q-warps) plus:
//  (1) patch prologue via cp.async.cg 16B (no LDG->reg->STS round trip,
//      overlaps the kr preloads); scalar clamped fallback only at image edges.
//  (2) u=32 partial row computed FIRST, its krS taps issued at kernel start
//      next to krA -> last unshadowed kernel-LDG burst removed. krS's live
//      range ends before krB starts, so peak kr registers stay at 33.

#define KW     33
#define BLK    4
#define PAD    16
#define HH     512
#define WW     512
#define HB     128
#define WBNUM  128
#define KSTR   (HB*WBNUM)         // 16384 elements between taps
#define TWB    32                 // wb blocks per CTA
#define PROWS  36                 // 4 + 2*16
#define PCOLS  160                // 32*4 + 2*16
#define PSTR   164                // row stride (floats), 656B (16B aligned)
#define NTHREADS 384
#define SMEM_FLOATS (3 * PROWS * PSTR)
#define SMEM_BYTES  (SMEM_FLOATS * 4)
#define NUNITS (3 * PROWS * (PCOLS/4))   // 4320 float4 units

__global__ __launch_bounds__(NTHREADS, 2)
void reblur_kernel(const float* __restrict__ img,
                   const float* __restrict__ ker,
                   float* __restrict__ out)
{
    extern __shared__ __align__(16) float sm[];
    unsigned int sbase;
    asm("{ .reg .u64 t; cvta.to.shared.u64 t, %1; cvt.u32.u64 %0, t; }"
        : "=r"(sbase) : "l"(sm));

    const int tid = threadIdx.x;
    const int WB0 = blockIdx.x * TWB;
    const int HB0 = blockIdx.y;

    // ---- work mapping: 12 warps = 3 channels x 4 u-quarters ----
    const int w    = tid >> 5;
    const int lane = tid & 31;    // wb block within tile
    const int c    = w >> 2;      // 0..2 channel
    const int q    = w & 3;       // 0..3 u-quarter (u = q mod 4, u < 32)
    const int wb4  = lane * BLK;

    // kernel tap t element: ker[t*KSTR + hb*WBNUM + wb]; lanes = consecutive wb
    const float* kbase = ker + HB0 * WBNUM + (WB0 + lane);

    // ---- issue krA (first u-row) and krS (u=32 slice) LDGs up front ----
    float krA[17], krS[9];
    {
        const float* kp = kbase + (q * KW) * KSTR;
#pragma unroll
        for (int v = 0; v < 17; v++)
            krA[v] = __ldg(kp + v * KSTR);
        const float* kps = kbase + (32 * KW + 8 * q) * KSTR;
#pragma unroll
        for (int i = 0; i < 8; i++)
            krS[i] = __ldg(kps + i * KSTR);
        krS[8] = (q == 3) ? __ldg(kbase + (32 * KW + 32) * KSTR) : 0.0f;
    }

    // ---- patch prologue: cp.async 16B for in-range units, scalar at edges ----
    const int row0 = HB0 * BLK - PAD;
    const int col0 = WB0 * BLK - PAD;
    for (int idx = tid; idx < NUNITS; idx += NTHREADS) {
        int cc0 = idx / (PROWS * 40);
        int rem = idx - cc0 * (PROWS * 40);
        int r   = rem / 40;
        int m   = rem - r * 40;
        int ir  = min(max(row0 + r, 0), HH - 1);
        int cs  = col0 + 4 * m;
        unsigned int dst = sbase + (unsigned)((cc0 * PROWS + r) * PSTR) * 4u
                         + (unsigned)m * 16u;
        if (cs >= 0 && cs + 4 <= WW) {
            const float* src = img + cc0 * (HH * WW) + ir * WW + cs;
            asm volatile("cp.async.cg.shared.global [%0], [%1], 16;"
                         :: "r"(dst), "l"(src));
        } else {
            const float* rowp = img + cc0 * (HH * WW) + ir * WW;
            float4 v;
            v.x = rowp[min(max(cs + 0, 0), WW - 1)];
            v.y = rowp[min(max(cs + 1, 0), WW - 1)];
            v.z = rowp[min(max(cs + 2, 0), WW - 1)];
            v.w = rowp[min(max(cs + 3, 0), WW - 1)];
            *reinterpret_cast<float4*>(
                sm + (cc0 * PROWS + r) * PSTR + 4 * m) = v;
        }
    }
    asm volatile("cp.async.commit_group;");
    asm volatile("cp.async.wait_group 0;" ::: "memory");
    __syncthreads();

    const float* spc = sm + c * (PROWS * PSTR);

    float acc[4][4];
#pragma unroll
    for (int i = 0; i < 4; i++)
#pragma unroll
        for (int j = 0; j < 4; j++)
            acc[i][j] = 0.0f;

    // ---- u=32 slice first: taps 8q..8q+7 (+ tap 32 for q==3) ----
#pragma unroll
    for (int oi = 0; oi < 4; oi++) {
        float rbS[12];   // cols (rel wb4) 8q .. 8q+11
        const float4* rp =
            reinterpret_cast<const float4*>(spc + (32 + oi) * PSTR + wb4 + 8 * q);
#pragma unroll
        for (int i = 0; i < 3; i++) {
            float4 t = rp[i];
            rbS[4*i+0] = t.x; rbS[4*i+1] = t.y;
            rbS[4*i+2] = t.z; rbS[4*i+3] = t.w;
        }
#pragma unroll
        for (int i = 0; i < 8; i++) {
            const float k = krS[i];
            acc[oi][0] += k * rbS[i + 0];
            acc[oi][1] += k * rbS[i + 1];
            acc[oi][2] += k * rbS[i + 2];
            acc[oi][3] += k * rbS[i + 3];
        }
        acc[oi][0] += krS[8] * rbS[8];
        acc[oi][1] += krS[8] * rbS[9];
        acc[oi][2] += krS[8] * rbS[10];
        acc[oi][3] += krS[8] * rbS[11];
    }

    // ---- main loop: u = q, q+4, ..., <32 (8 iterations) ----
    float krB[16];
#pragma unroll 1
    for (int u = q; u < 32; u += 4) {
        const float* kpu = kbase + (u * KW) * KSTR;
        // load krB (taps 17..32) — consumed only after halfA compute
#pragma unroll
        for (int v = 0; v < 16; v++)
            krB[v] = __ldg(kpu + (17 + v) * KSTR);

        // halfA: taps 0..16, window cols 0..19
#pragma unroll
        for (int oi = 0; oi < 4; oi++) {
            float rb[20];
            const float4* rp =
                reinterpret_cast<const float4*>(spc + (u + oi) * PSTR + wb4);
#pragma unroll
            for (int i = 0; i < 5; i++) {
                float4 t = rp[i];
                rb[4*i+0] = t.x; rb[4*i+1] = t.y;
                rb[4*i+2] = t.z; rb[4*i+3] = t.w;
            }
#pragma unroll
            for (int v = 0; v < 17; v++) {
                const float k = krA[v];
                acc[oi][0] += k * rb[v + 0];
                acc[oi][1] += k * rb[v + 1];
                acc[oi][2] += k * rb[v + 2];
                acc[oi][3] += k * rb[v + 3];
            }
        }

        // prefetch krA for u+4 (hidden under halfB compute)
        if (u + 4 < 32) {
            const float* kp2 = kbase + ((u + 4) * KW) * KSTR;
#pragma unroll
            for (int v = 0; v < 17; v++)
                krA[v] = __ldg(kp2 + v * KSTR);
        }

        // halfB: taps 17..32, window cols 16..35 (rb2[k] = col 16+k)
#pragma unroll
        for (int oi = 0; oi < 4; oi++) {
            float rb2[20];
            const float4* rp =
                reinterpret_cast<const float4*>(spc + (u + oi) * PSTR + wb4 + 16);
#pragma unroll
            for (int i = 0; i < 5; i++) {
                float4 t = rp[i];
                rb2[4*i+0] = t.x; rb2[4*i+1] = t.y;
                rb2[4*i+2] = t.z; rb2[4*i+3] = t.w;
            }
#pragma unroll
            for (int v = 0; v < 16; v++) {
                const float k = krB[v];
                acc[oi][0] += k * rb2[v + 1];
                acc[oi][1] += k * rb2[v + 2];
                acc[oi][2] += k * rb2[v + 3];
                acc[oi][3] += k * rb2[v + 4];
            }
        }
    }

    // ---- combine the 4 u-quarters via smem (reuse patch buffer) ----
    __syncthreads();               // everyone done reading the patch
    const int unit = c * 32 + lane;        // 0..95
    if (q != 0) {
        float* dst = sm + ((q - 1) * 96 + unit) * 16;
#pragma unroll
        for (int oi = 0; oi < 4; oi++) {
            float4 v = make_float4(acc[oi][0], acc[oi][1], acc[oi][2], acc[oi][3]);
            *reinterpret_cast<float4*>(dst + oi * 4) = v;
        }
    }
    __syncthreads();
    if (q == 0) {
#pragma unroll
        for (int p = 0; p < 3; p++) {
            const float* src = sm + (p * 96 + unit) * 16;
#pragma unroll
            for (int oi = 0; oi < 4; oi++) {
                float4 o = *reinterpret_cast<const float4*>(src + oi * 4);
                acc[oi][0] += o.x; acc[oi][1] += o.y;
                acc[oi][2] += o.z; acc[oi][3] += o.w;
            }
        }
        // coalesced store: 32 lanes x 16B = 512B contiguous per row
        float* ob = out + c * (HH * WW) + (HB0 * BLK) * WW + (WB0 + lane) * BLK;
#pragma unroll
        for (int oi = 0; oi < 4; oi++) {
            float4 val = make_float4(acc[oi][0], acc[oi][1], acc[oi][2], acc[oi][3]);
            *reinterpret_cast<float4*>(ob + oi * WW) = val;
        }
    }
}

extern "C" void kernel_launch(void* const* d_in, const int* in_sizes, int n_in,
                              void* d_out, int out_size)
{
    const float* img = (const float*)d_in[0];  // (1,3,512,512) fp32
    const float* ker = (const float*)d_in[1];  // (1,1089,128,128) fp32
    float* out = (float*)d_out;                // (1,3,512,512) fp32
    (void)in_sizes; (void)n_in; (void)out_size;

    cudaFuncSetAttribute(reblur_kernel,
                         cudaFuncAttributeMaxDynamicSharedMemorySize, SMEM_BYTES);

    dim3 grid(WBNUM / TWB, HB);  // (4, 128) = 512 CTAs
    reblur_kernel<<<grid, NTHREADS, SMEM_BYTES>>>(img, ker, out);
}